// round 7
// baseline (speedup 1.0000x reference)
#include <cuda_runtime.h>
#include <cuda_bf16.h>
#include <math.h>

// ---------------------------------------------------------------------------
// Problem constants (fixed by setup_inputs)
// ---------------------------------------------------------------------------
#define MAXN   20000
#define MAXE   340000   // 320000 edges + 20000 self loops
#define F_IN   128
#define HC1    256      // 8 heads * 32
#define C2     64
#define NSLOPE 0.2f

// ---------------------------------------------------------------------------
// Scratch (static __device__ globals; no allocation anywhere)
// ---------------------------------------------------------------------------
__device__ float g_xl1[MAXN * HC1];
__device__ float g_xr1[MAXN * HC1];
__device__ float g_h1 [MAXN * HC1];
__device__ float g_xl2[MAXN * C2];
__device__ float g_xr2[MAXN * C2];
__device__ float g_h2 [MAXN * C2];
__device__ int   g_counts[MAXN];
__device__ int   g_cursor[MAXN];
__device__ int   g_rowptr[MAXN + 1];
__device__ int   g_col   [MAXE + 32];
__device__ float g_psum  [128 * C2];
__device__ float g_psumsq[128 * C2];
__device__ float g_mean[C2];
__device__ float g_rstd[C2];

// ---------------------------------------------------------------------------
// CSR build
// ---------------------------------------------------------------------------
__global__ void zero_counts_k(int* counts, int n) {
    int i = blockIdx.x * blockDim.x + threadIdx.x;
    if (i < n) counts[i] = 0;
}

// 2 elements per thread; both loads then both atomics issued back-to-back
// (MLP=2 on the ATOMG path instead of 1).
__global__ void count_k(const int* ei, int E, int Nn, int* counts) {
    int total = E + Nn;
    int i0 = (blockIdx.x * blockDim.x + threadIdx.x) * 2;
    int i1 = i0 + 1;
    int d0 = -1, d1 = -1;
    if (i0 < total) d0 = (i0 < E) ? ei[E + i0] : (i0 - E);
    if (i1 < total) d1 = (i1 < E) ? ei[E + i1] : (i1 - E);
    if (d0 >= 0) atomicAdd(&counts[d0], 1);
    if (d1 >= 0) atomicAdd(&counts[d1], 1);
}

// Single block, 1024 threads. Thread t serially scans its contiguous chunk,
// block-scans the 1024 chunk totals (10 log steps), then writes prefixes.
__global__ void scan_k(const int* counts, int* rowptr, int* cursor, int Nn) {
    __shared__ int sh[1024];
    int t = threadIdx.x;
    int per = (Nn + 1023) >> 10;
    int beg = t * per;
    int end = min(beg + per, Nn);
    int sum = 0;
    for (int i = beg; i < end; i++) sum += counts[i];
    sh[t] = sum;
    __syncthreads();
    for (int off = 1; off < 1024; off <<= 1) {
        int v = (t >= off) ? sh[t - off] : 0;
        __syncthreads();
        sh[t] += v;
        __syncthreads();
    }
    int run = sh[t] - sum;   // exclusive prefix of this chunk
    for (int i = beg; i < end; i++) {
        int c = counts[i];
        rowptr[i] = run;
        cursor[i] = run;
        run += c;
    }
    if (t == 1023) rowptr[Nn] = sh[1023];
}

// 2 elements per thread; loads, then both atomics, then both stores.
__global__ void scatter_k(const int* ei, int E, int Nn, int* cursor, int* col) {
    int total = E + Nn;
    int i0 = (blockIdx.x * blockDim.x + threadIdx.x) * 2;
    int i1 = i0 + 1;
    int s0 = 0, d0 = -1, s1 = 0, d1 = -1;
    if (i0 < total) {
        if (i0 < E) { s0 = ei[i0]; d0 = ei[E + i0]; }
        else        { s0 = d0 = i0 - E; }
    }
    if (i1 < total) {
        if (i1 < E) { s1 = ei[i1]; d1 = ei[E + i1]; }
        else        { s1 = d1 = i1 - E; }
    }
    int p0 = -1, p1 = -1;
    if (d0 >= 0) p0 = atomicAdd(&cursor[d0], 1);
    if (d1 >= 0) p1 = atomicAdd(&cursor[d1], 1);
    if (p0 >= 0) col[p0] = s0;
    if (p1 >= 0) col[p1] = s1;
}

// ---------------------------------------------------------------------------
// Dual-B SGEMM, double-buffered (register prefetch):
// C0 = A @ B0, C1 = A @ B1 (A tile loaded once per iteration).
// Row major. BM=128, BN=64, BK=16, 256 threads, 8x4 register micro-tiles.
// ---------------------------------------------------------------------------
__global__ void __launch_bounds__(256)
sgemm_dual_k(const float* __restrict__ A,
             const float* __restrict__ B0, const float* __restrict__ B1,
             float* __restrict__ C0, float* __restrict__ C1,
             int M, int N, int K) {
    __shared__ float As [16][128];   // [k][m]
    __shared__ float Bs0[16][64];    // [k][n]
    __shared__ float Bs1[16][64];
    const int tid = threadIdx.x;
    const int tx = tid & 15;         // n quad  (0..15)
    const int ty = tid >> 4;         // m octet (0..15)
    const int row0 = blockIdx.y * 128;
    const int col0 = blockIdx.x * 64;

    float acc0[8][4] = {};
    float acc1[8][4] = {};

    // Per-thread load coordinates (fixed across iterations)
    int am[8], ak[8];
#pragma unroll
    for (int i = 0; i < 8; i++) {
        int idx = tid + i * 256;
        am[i] = idx >> 4;
        ak[i] = idx & 15;
    }
    int bk[4], bn[4];
#pragma unroll
    for (int i = 0; i < 4; i++) {
        int idx = tid + i * 256;
        bk[i] = idx >> 6;
        bn[i] = idx & 63;
    }

    // Prologue: load tile 0 into registers
    float ra[8], rb0[4], rb1[4];
#pragma unroll
    for (int i = 0; i < 8; i++) {
        int gm = row0 + am[i];
        ra[i] = (gm < M) ? A[(long)gm * K + ak[i]] : 0.f;
    }
#pragma unroll
    for (int i = 0; i < 4; i++) {
        long off = (long)bk[i] * N + col0 + bn[i];
        rb0[i] = B0[off];
        rb1[i] = B1[off];
    }

    for (int k0 = 0; k0 < K; k0 += 16) {
        // Commit prefetched tile to SMEM
#pragma unroll
        for (int i = 0; i < 8; i++) As[ak[i]][am[i]] = ra[i];
#pragma unroll
        for (int i = 0; i < 4; i++) { Bs0[bk[i]][bn[i]] = rb0[i]; Bs1[bk[i]][bn[i]] = rb1[i]; }
        __syncthreads();

        // Prefetch next tile into registers (overlaps with compute below)
        int k1 = k0 + 16;
        if (k1 < K) {
#pragma unroll
            for (int i = 0; i < 8; i++) {
                int gm = row0 + am[i];
                ra[i] = (gm < M) ? A[(long)gm * K + k1 + ak[i]] : 0.f;
            }
#pragma unroll
            for (int i = 0; i < 4; i++) {
                long off = (long)(k1 + bk[i]) * N + col0 + bn[i];
                rb0[i] = B0[off];
                rb1[i] = B1[off];
            }
        }

#pragma unroll
        for (int kk = 0; kk < 16; kk++) {
            float a[8], b0[4], b1[4];
#pragma unroll
            for (int i = 0; i < 8; i++) a[i] = As[kk][ty * 8 + i];
#pragma unroll
            for (int j = 0; j < 4; j++) { b0[j] = Bs0[kk][tx * 4 + j]; b1[j] = Bs1[kk][tx * 4 + j]; }
#pragma unroll
            for (int i = 0; i < 8; i++)
#pragma unroll
                for (int j = 0; j < 4; j++) {
                    acc0[i][j] += a[i] * b0[j];
                    acc1[i][j] += a[i] * b1[j];
                }
        }
        __syncthreads();
    }
#pragma unroll
    for (int i = 0; i < 8; i++) {
        int gm = row0 + ty * 8 + i;
        if (gm < M) {
            float4 v0 = make_float4(acc0[i][0], acc0[i][1], acc0[i][2], acc0[i][3]);
            float4 v1 = make_float4(acc1[i][0], acc1[i][1], acc1[i][2], acc1[i][3]);
            *(float4*)&C0[(long)gm * N + col0 + tx * 4] = v0;
            *(float4*)&C1[(long)gm * N + col0 + tx * 4] = v1;
        }
    }
}

// ---------------------------------------------------------------------------
// Layer-1 edge kernel: one warp per dst node. 8 heads x 32 ch = 256 values,
// 8 per lane (lane L owns channels 8L..8L+7, inside head L>>2).
// Segment softmax fused with aggregation (no max subtraction: scores O(1)).
// Software-pipelined: edge e+1's feature loads issue before edge e's math.
// ---------------------------------------------------------------------------
__global__ void gat_edge1_k(const float* __restrict__ xl, const float* __restrict__ xr,
                            const float* __restrict__ att, const float* __restrict__ bias,
                            float* __restrict__ hout,
                            const int* __restrict__ rowptr, const int* __restrict__ col,
                            int Nn) {
    __shared__ float s_att[HC1];
    __shared__ float s_b[HC1];
    if (threadIdx.x < HC1) { s_att[threadIdx.x] = att[threadIdx.x]; s_b[threadIdx.x] = bias[threadIdx.x]; }
    __syncthreads();

    int warp = threadIdx.x >> 5;
    int lane = threadIdx.x & 31;
    int d = blockIdx.x * (blockDim.x >> 5) + warp;
    if (d >= Nn) return;

    const int base = lane * 8;
    float xrv[8], a[8];
    {
        float4 t0 = *(const float4*)&xr[(long)d * HC1 + base];
        float4 t1 = *(const float4*)&xr[(long)d * HC1 + base + 4];
        xrv[0]=t0.x; xrv[1]=t0.y; xrv[2]=t0.z; xrv[3]=t0.w;
        xrv[4]=t1.x; xrv[5]=t1.y; xrv[6]=t1.z; xrv[7]=t1.w;
    }
#pragma unroll
    for (int j = 0; j < 8; j++) a[j] = s_att[base + j];

    float acc[8] = {0,0,0,0,0,0,0,0};
    float denom = 0.f;

    int beg = rowptr[d], end = rowptr[d + 1];
    float4 c0 = make_float4(0,0,0,0), c1 = make_float4(0,0,0,0);
    if (beg < end) {
        int s0 = col[beg];
        const float4* p = (const float4*)&xl[(long)s0 * HC1 + base];
        c0 = __ldg(p); c1 = __ldg(p + 1);
    }
    for (int e = beg; e < end; e++) {
        float4 n0 = make_float4(0,0,0,0), n1 = make_float4(0,0,0,0);
        if (e + 1 < end) {
            int sn = col[e + 1];
            const float4* p = (const float4*)&xl[(long)sn * HC1 + base];
            n0 = __ldg(p); n1 = __ldg(p + 1);
        }
        float xls[8] = {c0.x, c0.y, c0.z, c0.w, c1.x, c1.y, c1.z, c1.w};
        float sc = 0.f;
#pragma unroll
        for (int j = 0; j < 8; j++) {
            float u = xls[j] + xrv[j];
            float t = (u > 0.f) ? u : NSLOPE * u;
            sc += t * a[j];
        }
        // reduce across the 4-lane group forming one head
        sc += __shfl_xor_sync(0xffffffff, sc, 1);
        sc += __shfl_xor_sync(0xffffffff, sc, 2);
        float ex = __expf(sc);
        denom += ex;
#pragma unroll
        for (int j = 0; j < 8; j++) acc[j] += ex * xls[j];
        c0 = n0; c1 = n1;
    }
    float inv = 1.f / (denom + 1e-16f);
#pragma unroll
    for (int j = 0; j < 8; j++) {
        float v = acc[j] * inv + s_b[base + j];
        v = (v > 0.f) ? v : expm1f(v);   // ELU
        hout[(long)d * HC1 + base + j] = v;
    }
}

// ---------------------------------------------------------------------------
// Layer-2 edge kernel: one warp per dst, 1 head x 64 ch, 2 values per lane.
// ---------------------------------------------------------------------------
__global__ void gat_edge2_k(const float* __restrict__ xl, const float* __restrict__ xr,
                            const float* __restrict__ att, const float* __restrict__ bias,
                            float* __restrict__ hout,
                            const int* __restrict__ rowptr, const int* __restrict__ col,
                            int Nn) {
    __shared__ float s_att[C2];
    __shared__ float s_b[C2];
    if (threadIdx.x < C2) { s_att[threadIdx.x] = att[threadIdx.x]; s_b[threadIdx.x] = bias[threadIdx.x]; }
    __syncthreads();

    int warp = threadIdx.x >> 5;
    int lane = threadIdx.x & 31;
    int d = blockIdx.x * (blockDim.x >> 5) + warp;
    if (d >= Nn) return;

    const int base = lane * 2;
    float2 xrv = *(const float2*)&xr[(long)d * C2 + base];
    float a0 = s_att[base], a1 = s_att[base + 1];
    float acc0 = 0.f, acc1 = 0.f, denom = 0.f;

    int beg = rowptr[d], end = rowptr[d + 1];
    float2 cv = make_float2(0.f, 0.f);
    if (beg < end) {
        int s0 = col[beg];
        cv = __ldg((const float2*)&xl[(long)s0 * C2 + base]);
    }
    for (int e = beg; e < end; e++) {
        float2 nv = make_float2(0.f, 0.f);
        if (e + 1 < end) {
            int sn = col[e + 1];
            nv = __ldg((const float2*)&xl[(long)sn * C2 + base]);
        }
        float u0 = cv.x + xrv.x; float t0 = (u0 > 0.f) ? u0 : NSLOPE * u0;
        float u1 = cv.y + xrv.y; float t1 = (u1 > 0.f) ? u1 : NSLOPE * u1;
        float sc = t0 * a0 + t1 * a1;
#pragma unroll
        for (int off = 16; off > 0; off >>= 1)
            sc += __shfl_xor_sync(0xffffffff, sc, off);
        float ex = __expf(sc);
        denom += ex;
        acc0 += ex * cv.x;
        acc1 += ex * cv.y;
        cv = nv;
    }
    float inv = 1.f / (denom + 1e-16f);
    hout[(long)d * C2 + base]     = acc0 * inv + s_b[base];
    hout[(long)d * C2 + base + 1] = acc1 * inv + s_b[base + 1];
}

// ---------------------------------------------------------------------------
// InstanceNorm stats (deterministic two-level reduction) + norm + log_softmax
// ---------------------------------------------------------------------------
__global__ void in_partial_k(const float* __restrict__ h, float* psum, float* psumsq, int Nn) {
    int c = threadIdx.x & 63;
    int rg = threadIdx.x >> 6;   // 0..3
    float s = 0.f, s2 = 0.f;
    for (int r = blockIdx.x * 4 + rg; r < Nn; r += gridDim.x * 4) {
        float v = h[(long)r * C2 + c];
        s += v; s2 += v * v;
    }
    __shared__ float sh[256], sh2[256];
    sh[threadIdx.x] = s; sh2[threadIdx.x] = s2;
    __syncthreads();
    if (rg == 0) {
        s  = sh[c]  + sh[64 + c]  + sh[128 + c]  + sh[192 + c];
        s2 = sh2[c] + sh2[64 + c] + sh2[128 + c] + sh2[192 + c];
        psum[blockIdx.x * C2 + c]   = s;
        psumsq[blockIdx.x * C2 + c] = s2;
    }
}

__global__ void in_final_k(const float* psum, const float* psumsq,
                           float* meanv, float* rstdv, int Nn, int nb) {
    int c = threadIdx.x;
    if (c >= C2) return;
    float s = 0.f, s2 = 0.f;
    for (int b = 0; b < nb; b++) { s += psum[b * C2 + c]; s2 += psumsq[b * C2 + c]; }
    float m = s / (float)Nn;
    float var = s2 / (float)Nn - m * m;
    meanv[c] = m;
    rstdv[c] = rsqrtf(var + 1e-5f);
}

__global__ void norm_lsm_k(const float* __restrict__ h,
                           const float* __restrict__ meanv, const float* __restrict__ rstdv,
                           const float* __restrict__ gamma, const float* __restrict__ beta,
                           float* __restrict__ out, int Nn, long out_size) {
    __shared__ float sm[C2], sr[C2], sg[C2], sb[C2];
    if (threadIdx.x < C2) {
        sm[threadIdx.x] = meanv[threadIdx.x];
        sr[threadIdx.x] = rstdv[threadIdx.x];
        sg[threadIdx.x] = gamma[threadIdx.x];
        sb[threadIdx.x] = beta[threadIdx.x];
    }
    __syncthreads();

    int warp = threadIdx.x >> 5;
    int lane = threadIdx.x & 31;
    int r = blockIdx.x * (blockDim.x >> 5) + warp;
    if (r >= Nn) return;

    const int base = lane * 2;
    float2 v = *(const float2*)&h[(long)r * C2 + base];
    float y0 = (v.x - sm[base])     * sr[base]     * sg[base]     + sb[base];
    float y1 = (v.y - sm[base + 1]) * sr[base + 1] * sg[base + 1] + sb[base + 1];

    long NC = (long)Nn * C2;
    bool write_h = (out_size >= 2 * NC);
    if (write_h) {
        out[(long)r * C2 + base]     = y0;
        out[(long)r * C2 + base + 1] = y1;
    }
    // log_softmax over the 64 channels of this row
    float mx = fmaxf(y0, y1);
#pragma unroll
    for (int off = 16; off > 0; off >>= 1)
        mx = fmaxf(mx, __shfl_xor_sync(0xffffffff, mx, off));
    float s = __expf(y0 - mx) + __expf(y1 - mx);
#pragma unroll
    for (int off = 16; off > 0; off >>= 1)
        s += __shfl_xor_sync(0xffffffff, s, off);
    float lse = mx + __logf(s);

    float* out2 = out + (out_size - NC);
    out2[(long)r * C2 + base]     = y0 - lse;
    out2[(long)r * C2 + base + 1] = y1 - lse;
}

// ---------------------------------------------------------------------------
// Host launch
// ---------------------------------------------------------------------------
extern "C" void kernel_launch(void* const* d_in, const int* in_sizes, int n_in,
                              void* d_out, int out_size) {
    const float* x     = (const float*)d_in[0];
    const float* Wl1   = (const float*)d_in[1];
    const float* Wr1   = (const float*)d_in[2];
    const float* att1  = (const float*)d_in[3];
    const float* b1    = (const float*)d_in[4];
    const float* Wl2   = (const float*)d_in[5];
    const float* Wr2   = (const float*)d_in[6];
    const float* att2  = (const float*)d_in[7];
    const float* b2    = (const float*)d_in[8];
    const float* gamma = (const float*)d_in[9];
    const float* beta  = (const float*)d_in[10];
    const int*   ei    = (const int*)d_in[11];

    int Nn = in_sizes[0] / F_IN;        // 20000
    int E  = in_sizes[11] / 2;          // 320000
    if (Nn > MAXN) Nn = MAXN;
    if (E + Nn > MAXE) E = MAXE - Nn;

    float *xl1, *xr1, *h1, *xl2, *xr2, *h2, *psum, *psumsq, *meanv, *rstdv;
    int *counts, *cursor, *rowptr, *colv;
    cudaGetSymbolAddress((void**)&xl1, g_xl1);
    cudaGetSymbolAddress((void**)&xr1, g_xr1);
    cudaGetSymbolAddress((void**)&h1,  g_h1);
    cudaGetSymbolAddress((void**)&xl2, g_xl2);
    cudaGetSymbolAddress((void**)&xr2, g_xr2);
    cudaGetSymbolAddress((void**)&h2,  g_h2);
    cudaGetSymbolAddress((void**)&psum,   g_psum);
    cudaGetSymbolAddress((void**)&psumsq, g_psumsq);
    cudaGetSymbolAddress((void**)&meanv,  g_mean);
    cudaGetSymbolAddress((void**)&rstdv,  g_rstd);
    cudaGetSymbolAddress((void**)&counts, g_counts);
    cudaGetSymbolAddress((void**)&cursor, g_cursor);
    cudaGetSymbolAddress((void**)&rowptr, g_rowptr);
    cudaGetSymbolAddress((void**)&colv,   g_col);

    int total = E + Nn;

    // CSR build
    zero_counts_k<<<(Nn + 255) / 256, 256>>>(counts, Nn);
    count_k<<<(total / 2 + 256) / 256, 256>>>(ei, E, Nn, counts);
    scan_k<<<1, 1024>>>(counts, rowptr, cursor, Nn);
    scatter_k<<<(total / 2 + 256) / 256, 256>>>(ei, E, Nn, cursor, colv);

    // Layer 1 GEMMs: [N,128] @ [128,256] -> xl1, xr1 (A loaded once)
    {
        dim3 grid(HC1 / 64, (Nn + 127) / 128);
        sgemm_dual_k<<<grid, 256>>>(x, Wl1, Wr1, xl1, xr1, Nn, HC1, F_IN);
    }
    // Layer 1 attention + aggregate + bias + ELU
    gat_edge1_k<<<(Nn + 7) / 8, 256>>>(xl1, xr1, att1, b1, h1, rowptr, colv, Nn);

    // Layer 2 GEMMs: [N,256] @ [256,64] -> xl2, xr2
    {
        dim3 grid(C2 / 64, (Nn + 127) / 128);
        sgemm_dual_k<<<grid, 256>>>(h1, Wl2, Wr2, xl2, xr2, Nn, C2, HC1);
    }
    // Layer 2 attention + aggregate + bias
    gat_edge2_k<<<(Nn + 7) / 8, 256>>>(xl2, xr2, att2, b2, h2, rowptr, colv, Nn);

    // InstanceNorm stats
    in_partial_k<<<128, 256>>>(h2, psum, psumsq, Nn);
    in_final_k<<<1, 64>>>(psum, psumsq, meanv, rstdv, Nn, 128);

    // Normalize + log_softmax, write outputs
    norm_lsm_k<<<(Nn + 7) / 8, 256>>>(h2, meanv, rstdv, gamma, beta,
                                      (float*)d_out, Nn, (long)out_size);
}

// round 13
// speedup vs baseline: 1.2250x; 1.2250x over previous
#include <cuda_runtime.h>
#include <cuda_bf16.h>
#include <math.h>

// ---------------------------------------------------------------------------
// Problem constants (fixed by setup_inputs)
// ---------------------------------------------------------------------------
#define MAXN   20000
#define MAXE   340000   // 320000 edges + 20000 self loops
#define F_IN   128
#define HC1    256      // 8 heads * 32
#define C2     64
#define NSLOPE 0.2f

// ---------------------------------------------------------------------------
// Scratch (static __device__ globals; no allocation anywhere)
// ---------------------------------------------------------------------------
__device__ float g_xl1[MAXN * HC1];
__device__ float g_xr1[MAXN * HC1];
__device__ float g_h1 [MAXN * HC1];
__device__ float g_xl2[MAXN * C2];
__device__ float g_xr2[MAXN * C2];
__device__ float g_h2 [MAXN * C2];
__device__ int   g_counts[MAXN];
__device__ int   g_cursor[MAXN];
__device__ int   g_rowptr[MAXN + 1];
__device__ int   g_col   [MAXE + 32];
__device__ float g_psum  [128 * C2];
__device__ float g_psumsq[128 * C2];
__device__ float g_mean[C2];
__device__ float g_rstd[C2];

// ---------------------------------------------------------------------------
// CSR build (count/scatter: 1 element/thread — the measured-fastest form)
// ---------------------------------------------------------------------------
__global__ void zero_counts_k(int* counts, int n) {
    int i = blockIdx.x * blockDim.x + threadIdx.x;
    if (i < n) counts[i] = 0;
}

__global__ void count_k(const int* ei, int E, int Nn, int* counts) {
    int i = blockIdx.x * blockDim.x + threadIdx.x;
    int total = E + Nn;
    if (i >= total) return;
    int d = (i < E) ? ei[E + i] : (i - E);   // dst row of edge_index, or self loop
    atomicAdd(&counts[d], 1);
}

// Single block, 1024 threads. Thread t serially scans its contiguous chunk,
// block-scans the 1024 chunk totals (10 log steps), then writes prefixes.
__global__ void scan_k(const int* counts, int* rowptr, int* cursor, int Nn) {
    __shared__ int sh[1024];
    int t = threadIdx.x;
    int per = (Nn + 1023) >> 10;
    int beg = t * per;
    int end = min(beg + per, Nn);
    int sum = 0;
    for (int i = beg; i < end; i++) sum += counts[i];
    sh[t] = sum;
    __syncthreads();
    for (int off = 1; off < 1024; off <<= 1) {
        int v = (t >= off) ? sh[t - off] : 0;
        __syncthreads();
        sh[t] += v;
        __syncthreads();
    }
    int run = sh[t] - sum;   // exclusive prefix of this chunk
    for (int i = beg; i < end; i++) {
        int c = counts[i];
        rowptr[i] = run;
        cursor[i] = run;
        run += c;
    }
    if (t == 1023) rowptr[Nn] = sh[1023];
}

__global__ void scatter_k(const int* ei, int E, int Nn, int* cursor, int* col) {
    int i = blockIdx.x * blockDim.x + threadIdx.x;
    int total = E + Nn;
    if (i >= total) return;
    int s, d;
    if (i < E) { s = ei[i]; d = ei[E + i]; }
    else       { s = d = i - E; }
    int pos = atomicAdd(&cursor[d], 1);
    col[pos] = s;
}

// ---------------------------------------------------------------------------
// Dual-B SGEMM at the measured-good 64x64/4x4 operating point:
// C0 = A @ B0, C1 = A @ B1 (A tile loaded once). BK=16, 256 threads.
// Register cost ~60/thread (32 acc + fragments) — no spill risk.
// ---------------------------------------------------------------------------
__global__ void sgemm_dual_k(const float* __restrict__ A,
                             const float* __restrict__ B0, const float* __restrict__ B1,
                             float* __restrict__ C0, float* __restrict__ C1,
                             int M, int N, int K) {
    __shared__ float As [16][65];   // [k][m], padded
    __shared__ float Bs0[16][64];   // [k][n]
    __shared__ float Bs1[16][64];
    const int tid = threadIdx.x;
    const int tx = tid % 16;       // n quad
    const int ty = tid / 16;       // m quad
    const int row0 = blockIdx.y * 64;
    const int col0 = blockIdx.x * 64;

    float acc0[4][4] = {};
    float acc1[4][4] = {};
    for (int k0 = 0; k0 < K; k0 += 16) {
#pragma unroll
        for (int i = 0; i < 4; i++) {
            int idx = tid + i * 256;          // 0..1023
            int m = idx >> 4;                  // /16
            int kk = idx & 15;
            int gm = row0 + m;
            As[kk][m] = (gm < M) ? A[(long)gm * K + k0 + kk] : 0.f;
        }
#pragma unroll
        for (int i = 0; i < 4; i++) {
            int idx = tid + i * 256;
            int kk = idx >> 6;                 // /64
            int n = idx & 63;
            long off = (long)(k0 + kk) * N + col0 + n;
            Bs0[kk][n] = B0[off];
            Bs1[kk][n] = B1[off];
        }
        __syncthreads();
#pragma unroll
        for (int kk = 0; kk < 16; kk++) {
            float a[4], b0[4], b1[4];
#pragma unroll
            for (int i = 0; i < 4; i++) a[i] = As[kk][ty * 4 + i];
#pragma unroll
            for (int j = 0; j < 4; j++) { b0[j] = Bs0[kk][tx * 4 + j]; b1[j] = Bs1[kk][tx * 4 + j]; }
#pragma unroll
            for (int i = 0; i < 4; i++)
#pragma unroll
                for (int j = 0; j < 4; j++) {
                    acc0[i][j] += a[i] * b0[j];
                    acc1[i][j] += a[i] * b1[j];
                }
        }
        __syncthreads();
    }
#pragma unroll
    for (int i = 0; i < 4; i++) {
        int gm = row0 + ty * 4 + i;
        if (gm < M) {
            float4 v0 = make_float4(acc0[i][0], acc0[i][1], acc0[i][2], acc0[i][3]);
            float4 v1 = make_float4(acc1[i][0], acc1[i][1], acc1[i][2], acc1[i][3]);
            *(float4*)&C0[(long)gm * N + col0 + tx * 4] = v0;
            *(float4*)&C1[(long)gm * N + col0 + tx * 4] = v1;
        }
    }
}

// ---------------------------------------------------------------------------
// Layer-1 edge kernel (measured R2 form): one warp per dst node.
// 8 heads x 32 ch = 256 values, 8 per lane; index-only prefetch.
// ---------------------------------------------------------------------------
__global__ void gat_edge1_k(const float* __restrict__ xl, const float* __restrict__ xr,
                            const float* __restrict__ att, const float* __restrict__ bias,
                            float* __restrict__ hout,
                            const int* __restrict__ rowptr, const int* __restrict__ col,
                            int Nn) {
    __shared__ float s_att[HC1];
    __shared__ float s_b[HC1];
    if (threadIdx.x < HC1) { s_att[threadIdx.x] = att[threadIdx.x]; s_b[threadIdx.x] = bias[threadIdx.x]; }
    __syncthreads();

    int warp = threadIdx.x >> 5;
    int lane = threadIdx.x & 31;
    int d = blockIdx.x * (blockDim.x >> 5) + warp;
    if (d >= Nn) return;

    const int base = lane * 8;
    float xrv[8], a[8];
    {
        float4 t0 = *(const float4*)&xr[(long)d * HC1 + base];
        float4 t1 = *(const float4*)&xr[(long)d * HC1 + base + 4];
        xrv[0]=t0.x; xrv[1]=t0.y; xrv[2]=t0.z; xrv[3]=t0.w;
        xrv[4]=t1.x; xrv[5]=t1.y; xrv[6]=t1.z; xrv[7]=t1.w;
    }
#pragma unroll
    for (int j = 0; j < 8; j++) a[j] = s_att[base + j];

    float acc[8] = {0,0,0,0,0,0,0,0};
    float denom = 0.f;

    int beg = rowptr[d], end = rowptr[d + 1];
    int s_next = (beg < end) ? col[beg] : 0;
    for (int e = beg; e < end; e++) {
        int s = s_next;
        if (e + 1 < end) s_next = col[e + 1];           // prefetch next index
        const float4* p = (const float4*)&xl[(long)s * HC1 + base];
        float4 v0 = __ldg(p);
        float4 v1 = __ldg(p + 1);
        float xls[8] = {v0.x, v0.y, v0.z, v0.w, v1.x, v1.y, v1.z, v1.w};
        float sc = 0.f;
#pragma unroll
        for (int j = 0; j < 8; j++) {
            float u = xls[j] + xrv[j];
            float t = (u > 0.f) ? u : NSLOPE * u;
            sc += t * a[j];
        }
        // reduce across the 4-lane group that forms one head
        sc += __shfl_xor_sync(0xffffffff, sc, 1);
        sc += __shfl_xor_sync(0xffffffff, sc, 2);
        float ex = __expf(sc);
        denom += ex;
#pragma unroll
        for (int j = 0; j < 8; j++) acc[j] += ex * xls[j];
    }
    float inv = 1.f / (denom + 1e-16f);
#pragma unroll
    for (int j = 0; j < 8; j++) {
        float v = acc[j] * inv + s_b[base + j];
        v = (v > 0.f) ? v : expm1f(v);   // ELU
        hout[(long)d * HC1 + base + j] = v;
    }
}

// ---------------------------------------------------------------------------
// Layer-2 edge kernel (measured R2 form): one warp per dst, 2 values/lane.
// ---------------------------------------------------------------------------
__global__ void gat_edge2_k(const float* __restrict__ xl, const float* __restrict__ xr,
                            const float* __restrict__ att, const float* __restrict__ bias,
                            float* __restrict__ hout,
                            const int* __restrict__ rowptr, const int* __restrict__ col,
                            int Nn) {
    __shared__ float s_att[C2];
    __shared__ float s_b[C2];
    if (threadIdx.x < C2) { s_att[threadIdx.x] = att[threadIdx.x]; s_b[threadIdx.x] = bias[threadIdx.x]; }
    __syncthreads();

    int warp = threadIdx.x >> 5;
    int lane = threadIdx.x & 31;
    int d = blockIdx.x * (blockDim.x >> 5) + warp;
    if (d >= Nn) return;

    const int base = lane * 2;
    float2 xrv = *(const float2*)&xr[(long)d * C2 + base];
    float a0 = s_att[base], a1 = s_att[base + 1];
    float acc0 = 0.f, acc1 = 0.f, denom = 0.f;

    int beg = rowptr[d], end = rowptr[d + 1];
    int s_next = (beg < end) ? col[beg] : 0;
    for (int e = beg; e < end; e++) {
        int s = s_next;
        if (e + 1 < end) s_next = col[e + 1];
        float2 v = __ldg((const float2*)&xl[(long)s * C2 + base]);
        float u0 = v.x + xrv.x; float t0 = (u0 > 0.f) ? u0 : NSLOPE * u0;
        float u1 = v.y + xrv.y; float t1 = (u1 > 0.f) ? u1 : NSLOPE * u1;
        float sc = t0 * a0 + t1 * a1;
#pragma unroll
        for (int off = 16; off > 0; off >>= 1)
            sc += __shfl_xor_sync(0xffffffff, sc, off);
        float ex = __expf(sc);
        denom += ex;
        acc0 += ex * v.x;
        acc1 += ex * v.y;
    }
    float inv = 1.f / (denom + 1e-16f);
    hout[(long)d * C2 + base]     = acc0 * inv + s_b[base];
    hout[(long)d * C2 + base + 1] = acc1 * inv + s_b[base + 1];
}

// ---------------------------------------------------------------------------
// InstanceNorm stats (deterministic two-level reduction) + norm + log_softmax
// ---------------------------------------------------------------------------
__global__ void in_partial_k(const float* __restrict__ h, float* psum, float* psumsq, int Nn) {
    int c = threadIdx.x & 63;
    int rg = threadIdx.x >> 6;   // 0..3
    float s = 0.f, s2 = 0.f;
    for (int r = blockIdx.x * 4 + rg; r < Nn; r += gridDim.x * 4) {
        float v = h[(long)r * C2 + c];
        s += v; s2 += v * v;
    }
    __shared__ float sh[256], sh2[256];
    sh[threadIdx.x] = s; sh2[threadIdx.x] = s2;
    __syncthreads();
    if (rg == 0) {
        s  = sh[c]  + sh[64 + c]  + sh[128 + c]  + sh[192 + c];
        s2 = sh2[c] + sh2[64 + c] + sh2[128 + c] + sh2[192 + c];
        psum[blockIdx.x * C2 + c]   = s;
        psumsq[blockIdx.x * C2 + c] = s2;
    }
}

__global__ void in_final_k(const float* psum, const float* psumsq,
                           float* meanv, float* rstdv, int Nn, int nb) {
    int c = threadIdx.x;
    if (c >= C2) return;
    float s = 0.f, s2 = 0.f;
    for (int b = 0; b < nb; b++) { s += psum[b * C2 + c]; s2 += psumsq[b * C2 + c]; }
    float m = s / (float)Nn;
    float var = s2 / (float)Nn - m * m;
    meanv[c] = m;
    rstdv[c] = rsqrtf(var + 1e-5f);
}

__global__ void norm_lsm_k(const float* __restrict__ h,
                           const float* __restrict__ meanv, const float* __restrict__ rstdv,
                           const float* __restrict__ gamma, const float* __restrict__ beta,
                           float* __restrict__ out, int Nn, long out_size) {
    __shared__ float sm[C2], sr[C2], sg[C2], sb[C2];
    if (threadIdx.x < C2) {
        sm[threadIdx.x] = meanv[threadIdx.x];
        sr[threadIdx.x] = rstdv[threadIdx.x];
        sg[threadIdx.x] = gamma[threadIdx.x];
        sb[threadIdx.x] = beta[threadIdx.x];
    }
    __syncthreads();

    int warp = threadIdx.x >> 5;
    int lane = threadIdx.x & 31;
    int r = blockIdx.x * (blockDim.x >> 5) + warp;
    if (r >= Nn) return;

    const int base = lane * 2;
    float2 v = *(const float2*)&h[(long)r * C2 + base];
    float y0 = (v.x - sm[base])     * sr[base]     * sg[base]     + sb[base];
    float y1 = (v.y - sm[base + 1]) * sr[base + 1] * sg[base + 1] + sb[base + 1];

    long NC = (long)Nn * C2;
    bool write_h = (out_size >= 2 * NC);
    if (write_h) {
        out[(long)r * C2 + base]     = y0;
        out[(long)r * C2 + base + 1] = y1;
    }
    // log_softmax over the 64 channels of this row
    float mx = fmaxf(y0, y1);
#pragma unroll
    for (int off = 16; off > 0; off >>= 1)
        mx = fmaxf(mx, __shfl_xor_sync(0xffffffff, mx, off));
    float s = __expf(y0 - mx) + __expf(y1 - mx);
#pragma unroll
    for (int off = 16; off > 0; off >>= 1)
        s += __shfl_xor_sync(0xffffffff, s, off);
    float lse = mx + __logf(s);

    float* out2 = out + (out_size - NC);
    out2[(long)r * C2 + base]     = y0 - lse;
    out2[(long)r * C2 + base + 1] = y1 - lse;
}

// ---------------------------------------------------------------------------
// Host launch
// ---------------------------------------------------------------------------
extern "C" void kernel_launch(void* const* d_in, const int* in_sizes, int n_in,
                              void* d_out, int out_size) {
    const float* x     = (const float*)d_in[0];
    const float* Wl1   = (const float*)d_in[1];
    const float* Wr1   = (const float*)d_in[2];
    const float* att1  = (const float*)d_in[3];
    const float* b1    = (const float*)d_in[4];
    const float* Wl2   = (const float*)d_in[5];
    const float* Wr2   = (const float*)d_in[6];
    const float* att2  = (const float*)d_in[7];
    const float* b2    = (const float*)d_in[8];
    const float* gamma = (const float*)d_in[9];
    const float* beta  = (const float*)d_in[10];
    const int*   ei    = (const int*)d_in[11];

    int Nn = in_sizes[0] / F_IN;        // 20000
    int E  = in_sizes[11] / 2;          // 320000
    if (Nn > MAXN) Nn = MAXN;
    if (E + Nn > MAXE) E = MAXE - Nn;

    float *xl1, *xr1, *h1, *xl2, *xr2, *h2, *psum, *psumsq, *meanv, *rstdv;
    int *counts, *cursor, *rowptr, *colv;
    cudaGetSymbolAddress((void**)&xl1, g_xl1);
    cudaGetSymbolAddress((void**)&xr1, g_xr1);
    cudaGetSymbolAddress((void**)&h1,  g_h1);
    cudaGetSymbolAddress((void**)&xl2, g_xl2);
    cudaGetSymbolAddress((void**)&xr2, g_xr2);
    cudaGetSymbolAddress((void**)&h2,  g_h2);
    cudaGetSymbolAddress((void**)&psum,   g_psum);
    cudaGetSymbolAddress((void**)&psumsq, g_psumsq);
    cudaGetSymbolAddress((void**)&meanv,  g_mean);
    cudaGetSymbolAddress((void**)&rstdv,  g_rstd);
    cudaGetSymbolAddress((void**)&counts, g_counts);
    cudaGetSymbolAddress((void**)&cursor, g_cursor);
    cudaGetSymbolAddress((void**)&rowptr, g_rowptr);
    cudaGetSymbolAddress((void**)&colv,   g_col);

    int total = E + Nn;

    // CSR build
    zero_counts_k<<<(Nn + 255) / 256, 256>>>(counts, Nn);
    count_k<<<(total + 255) / 256, 256>>>(ei, E, Nn, counts);
    scan_k<<<1, 1024>>>(counts, rowptr, cursor, Nn);
    scatter_k<<<(total + 255) / 256, 256>>>(ei, E, Nn, cursor, colv);

    // Layer 1 GEMMs: [N,128] @ [128,256] -> xl1, xr1 (A loaded once)
    {
        dim3 grid(HC1 / 64, (Nn + 63) / 64);
        sgemm_dual_k<<<grid, 256>>>(x, Wl1, Wr1, xl1, xr1, Nn, HC1, F_IN);
    }
    // Layer 1 attention + aggregate + bias + ELU
    gat_edge1_k<<<(Nn + 7) / 8, 256>>>(xl1, xr1, att1, b1, h1, rowptr, colv, Nn);

    // Layer 2 GEMMs: [N,256] @ [256,64] -> xl2, xr2
    {
        dim3 grid(C2 / 64, (Nn + 63) / 64);
        sgemm_dual_k<<<grid, 256>>>(h1, Wl2, Wr2, xl2, xr2, Nn, C2, HC1);
    }
    // Layer 2 attention + aggregate + bias
    gat_edge2_k<<<(Nn + 7) / 8, 256>>>(xl2, xr2, att2, b2, h2, rowptr, colv, Nn);

    // InstanceNorm stats
    in_partial_k<<<128, 256>>>(h2, psum, psumsq, Nn);
    in_final_k<<<1, 64>>>(psum, psumsq, meanv, rstdv, Nn, 128);

    // Normalize + log_softmax, write outputs
    norm_lsm_k<<<(Nn + 7) / 8, 256>>>(h2, meanv, rstdv, gamma, beta,
                                      (float*)d_out, Nn, (long)out_size);
}

// round 14
// speedup vs baseline: 1.2910x; 1.0538x over previous
#include <cuda_runtime.h>
#include <cuda_bf16.h>
#include <math.h>

// ---------------------------------------------------------------------------
// Problem constants (fixed by setup_inputs)
// ---------------------------------------------------------------------------
#define MAXN   20000
#define MAXE   340000   // 320000 edges + 20000 self loops
#define F_IN   128
#define HC1    256      // 8 heads * 32
#define C2     64
#define NSLOPE 0.2f

// ---------------------------------------------------------------------------
// Scratch (static __device__ globals; no allocation anywhere)
// ---------------------------------------------------------------------------
__device__ float g_xl1[MAXN * HC1];
__device__ float g_xr1[MAXN * HC1];
__device__ float g_h1 [MAXN * HC1];
__device__ float g_xl2[MAXN * C2];
__device__ float g_xr2[MAXN * C2];
__device__ float g_h2 [MAXN * C2];
__device__ int   g_counts[MAXN];
__device__ int   g_cursor[MAXN];
__device__ int   g_rowptr[MAXN + 1];
__device__ int   g_col   [MAXE + 32];
__device__ float g_psum  [128 * C2];
__device__ float g_psumsq[128 * C2];
__device__ float g_mean[C2];
__device__ float g_rstd[C2];

// ---------------------------------------------------------------------------
// CSR build (measured form)
// ---------------------------------------------------------------------------
__global__ void zero_counts_k(int* counts, int n) {
    int i = blockIdx.x * blockDim.x + threadIdx.x;
    if (i < n) counts[i] = 0;
}

__global__ void count_k(const int* ei, int E, int Nn, int* counts) {
    int i = blockIdx.x * blockDim.x + threadIdx.x;
    int total = E + Nn;
    if (i >= total) return;
    int d = (i < E) ? ei[E + i] : (i - E);   // dst row of edge_index, or self loop
    atomicAdd(&counts[d], 1);
}

// Single block, 1024 threads; serial chunk scan + 10-step block scan (validated R13).
__global__ void scan_k(const int* counts, int* rowptr, int* cursor, int Nn) {
    __shared__ int sh[1024];
    int t = threadIdx.x;
    int per = (Nn + 1023) >> 10;
    int beg = t * per;
    int end = min(beg + per, Nn);
    int sum = 0;
    for (int i = beg; i < end; i++) sum += counts[i];
    sh[t] = sum;
    __syncthreads();
    for (int off = 1; off < 1024; off <<= 1) {
        int v = (t >= off) ? sh[t - off] : 0;
        __syncthreads();
        sh[t] += v;
        __syncthreads();
    }
    int run = sh[t] - sum;   // exclusive prefix of this chunk
    for (int i = beg; i < end; i++) {
        int c = counts[i];
        rowptr[i] = run;
        cursor[i] = run;
        run += c;
    }
    if (t == 1023) rowptr[Nn] = sh[1023];
}

__global__ void scatter_k(const int* ei, int E, int Nn, int* cursor, int* col) {
    int i = blockIdx.x * blockDim.x + threadIdx.x;
    int total = E + Nn;
    if (i >= total) return;
    int s, d;
    if (i < E) { s = ei[i]; d = ei[E + i]; }
    else       { s = d = i - E; }
    int pos = atomicAdd(&cursor[d], 1);
    col[pos] = s;
}

// ---------------------------------------------------------------------------
// Dual-B SGEMM, 64x64/4x4 (validated), now with register-prefetch double
// buffering: tile k+1 loads issue while tile k computes. +12 regs (~75 total,
// still 3 CTAs/SM).
// ---------------------------------------------------------------------------
__global__ void sgemm_dual_k(const float* __restrict__ A,
                             const float* __restrict__ B0, const float* __restrict__ B1,
                             float* __restrict__ C0, float* __restrict__ C1,
                             int M, int N, int K) {
    __shared__ float As [16][65];   // [k][m], padded
    __shared__ float Bs0[16][64];   // [k][n]
    __shared__ float Bs1[16][64];
    const int tid = threadIdx.x;
    const int tx = tid % 16;       // n quad
    const int ty = tid / 16;       // m quad
    const int row0 = blockIdx.y * 64;
    const int col0 = blockIdx.x * 64;

    // Fixed per-thread load coordinates
    int am[4], ak[4], bk[4], bn[4];
#pragma unroll
    for (int i = 0; i < 4; i++) {
        int idx = tid + i * 256;
        am[i] = idx >> 4;
        ak[i] = idx & 15;
        bk[i] = idx >> 6;
        bn[i] = idx & 63;
    }

    float acc0[4][4] = {};
    float acc1[4][4] = {};

    // Prologue: tile 0 -> registers
    float ra[4], rb0[4], rb1[4];
#pragma unroll
    for (int i = 0; i < 4; i++) {
        int gm = row0 + am[i];
        ra[i] = (gm < M) ? A[(long)gm * K + ak[i]] : 0.f;
        long off = (long)bk[i] * N + col0 + bn[i];
        rb0[i] = B0[off];
        rb1[i] = B1[off];
    }

    for (int k0 = 0; k0 < K; k0 += 16) {
        // Commit prefetched tile to SMEM
#pragma unroll
        for (int i = 0; i < 4; i++) {
            As[ak[i]][am[i]]  = ra[i];
            Bs0[bk[i]][bn[i]] = rb0[i];
            Bs1[bk[i]][bn[i]] = rb1[i];
        }
        __syncthreads();

        // Prefetch next tile into registers (overlaps with compute)
        int k1 = k0 + 16;
        if (k1 < K) {
#pragma unroll
            for (int i = 0; i < 4; i++) {
                int gm = row0 + am[i];
                ra[i] = (gm < M) ? A[(long)gm * K + k1 + ak[i]] : 0.f;
                long off = (long)(k1 + bk[i]) * N + col0 + bn[i];
                rb0[i] = B0[off];
                rb1[i] = B1[off];
            }
        }

#pragma unroll
        for (int kk = 0; kk < 16; kk++) {
            float a[4], b0[4], b1[4];
#pragma unroll
            for (int i = 0; i < 4; i++) a[i] = As[kk][ty * 4 + i];
#pragma unroll
            for (int j = 0; j < 4; j++) { b0[j] = Bs0[kk][tx * 4 + j]; b1[j] = Bs1[kk][tx * 4 + j]; }
#pragma unroll
            for (int i = 0; i < 4; i++)
#pragma unroll
                for (int j = 0; j < 4; j++) {
                    acc0[i][j] += a[i] * b0[j];
                    acc1[i][j] += a[i] * b1[j];
                }
        }
        __syncthreads();
    }
#pragma unroll
    for (int i = 0; i < 4; i++) {
        int gm = row0 + ty * 4 + i;
        if (gm < M) {
            float4 v0 = make_float4(acc0[i][0], acc0[i][1], acc0[i][2], acc0[i][3]);
            float4 v1 = make_float4(acc1[i][0], acc1[i][1], acc1[i][2], acc1[i][3]);
            *(float4*)&C0[(long)gm * N + col0 + tx * 4] = v0;
            *(float4*)&C1[(long)gm * N + col0 + tx * 4] = v1;
        }
    }
}

// ---------------------------------------------------------------------------
// Layer-1 edge kernel: one warp per dst; 2 edges per iteration (MLP=2 on the
// gather path) with next-pair index prefetch. Accumulation order preserved
// (edge e before e+1).
// ---------------------------------------------------------------------------
__global__ void gat_edge1_k(const float* __restrict__ xl, const float* __restrict__ xr,
                            const float* __restrict__ att, const float* __restrict__ bias,
                            float* __restrict__ hout,
                            const int* __restrict__ rowptr, const int* __restrict__ col,
                            int Nn) {
    __shared__ float s_att[HC1];
    __shared__ float s_b[HC1];
    if (threadIdx.x < HC1) { s_att[threadIdx.x] = att[threadIdx.x]; s_b[threadIdx.x] = bias[threadIdx.x]; }
    __syncthreads();

    int warp = threadIdx.x >> 5;
    int lane = threadIdx.x & 31;
    int d = blockIdx.x * (blockDim.x >> 5) + warp;
    if (d >= Nn) return;

    const int base = lane * 8;
    float xrv[8], a[8];
    {
        float4 t0 = *(const float4*)&xr[(long)d * HC1 + base];
        float4 t1 = *(const float4*)&xr[(long)d * HC1 + base + 4];
        xrv[0]=t0.x; xrv[1]=t0.y; xrv[2]=t0.z; xrv[3]=t0.w;
        xrv[4]=t1.x; xrv[5]=t1.y; xrv[6]=t1.z; xrv[7]=t1.w;
    }
#pragma unroll
    for (int j = 0; j < 8; j++) a[j] = s_att[base + j];

    float acc[8] = {0,0,0,0,0,0,0,0};
    float denom = 0.f;

    int beg = rowptr[d], end = rowptr[d + 1];
    int sA = (beg < end) ? col[beg] : 0;
    int sB = (beg + 1 < end) ? col[beg + 1] : 0;

    int e = beg;
    while (e < end) {
        bool has2 = (e + 1 < end);
        // Prefetch next pair's indices
        int sA2 = (e + 2 < end) ? col[e + 2] : 0;
        int sB2 = (e + 3 < end) ? col[e + 3] : 0;

        // Issue both edges' feature loads back-to-back (MLP=2)
        const float4* pA = (const float4*)&xl[(long)sA * HC1 + base];
        float4 va0 = __ldg(pA);
        float4 va1 = __ldg(pA + 1);
        float4 vb0 = make_float4(0,0,0,0), vb1 = make_float4(0,0,0,0);
        if (has2) {
            const float4* pB = (const float4*)&xl[(long)sB * HC1 + base];
            vb0 = __ldg(pB);
            vb1 = __ldg(pB + 1);
        }

        // Edge A
        {
            float xls[8] = {va0.x, va0.y, va0.z, va0.w, va1.x, va1.y, va1.z, va1.w};
            float sc = 0.f;
#pragma unroll
            for (int j = 0; j < 8; j++) {
                float u = xls[j] + xrv[j];
                float t = (u > 0.f) ? u : NSLOPE * u;
                sc += t * a[j];
            }
            sc += __shfl_xor_sync(0xffffffff, sc, 1);
            sc += __shfl_xor_sync(0xffffffff, sc, 2);
            float ex = __expf(sc);
            denom += ex;
#pragma unroll
            for (int j = 0; j < 8; j++) acc[j] += ex * xls[j];
        }
        // Edge B
        if (has2) {
            float xls[8] = {vb0.x, vb0.y, vb0.z, vb0.w, vb1.x, vb1.y, vb1.z, vb1.w};
            float sc = 0.f;
#pragma unroll
            for (int j = 0; j < 8; j++) {
                float u = xls[j] + xrv[j];
                float t = (u > 0.f) ? u : NSLOPE * u;
                sc += t * a[j];
            }
            sc += __shfl_xor_sync(0xffffffff, sc, 1);
            sc += __shfl_xor_sync(0xffffffff, sc, 2);
            float ex = __expf(sc);
            denom += ex;
#pragma unroll
            for (int j = 0; j < 8; j++) acc[j] += ex * xls[j];
        }

        sA = sA2; sB = sB2;
        e += 2;
    }
    float inv = 1.f / (denom + 1e-16f);
#pragma unroll
    for (int j = 0; j < 8; j++) {
        float v = acc[j] * inv + s_b[base + j];
        v = (v > 0.f) ? v : expm1f(v);   // ELU
        hout[(long)d * HC1 + base + j] = v;
    }
}

// ---------------------------------------------------------------------------
// Layer-2 edge kernel (measured form): one warp per dst, 2 values/lane.
// ---------------------------------------------------------------------------
__global__ void gat_edge2_k(const float* __restrict__ xl, const float* __restrict__ xr,
                            const float* __restrict__ att, const float* __restrict__ bias,
                            float* __restrict__ hout,
                            const int* __restrict__ rowptr, const int* __restrict__ col,
                            int Nn) {
    __shared__ float s_att[C2];
    __shared__ float s_b[C2];
    if (threadIdx.x < C2) { s_att[threadIdx.x] = att[threadIdx.x]; s_b[threadIdx.x] = bias[threadIdx.x]; }
    __syncthreads();

    int warp = threadIdx.x >> 5;
    int lane = threadIdx.x & 31;
    int d = blockIdx.x * (blockDim.x >> 5) + warp;
    if (d >= Nn) return;

    const int base = lane * 2;
    float2 xrv = *(const float2*)&xr[(long)d * C2 + base];
    float a0 = s_att[base], a1 = s_att[base + 1];
    float acc0 = 0.f, acc1 = 0.f, denom = 0.f;

    int beg = rowptr[d], end = rowptr[d + 1];
    int s_next = (beg < end) ? col[beg] : 0;
    for (int e = beg; e < end; e++) {
        int s = s_next;
        if (e + 1 < end) s_next = col[e + 1];
        float2 v = __ldg((const float2*)&xl[(long)s * C2 + base]);
        float u0 = v.x + xrv.x; float t0 = (u0 > 0.f) ? u0 : NSLOPE * u0;
        float u1 = v.y + xrv.y; float t1 = (u1 > 0.f) ? u1 : NSLOPE * u1;
        float sc = t0 * a0 + t1 * a1;
#pragma unroll
        for (int off = 16; off > 0; off >>= 1)
            sc += __shfl_xor_sync(0xffffffff, sc, off);
        float ex = __expf(sc);
        denom += ex;
        acc0 += ex * v.x;
        acc1 += ex * v.y;
    }
    float inv = 1.f / (denom + 1e-16f);
    hout[(long)d * C2 + base]     = acc0 * inv + s_b[base];
    hout[(long)d * C2 + base + 1] = acc1 * inv + s_b[base + 1];
}

// ---------------------------------------------------------------------------
// InstanceNorm stats (deterministic two-level reduction) + norm + log_softmax
// ---------------------------------------------------------------------------
__global__ void in_partial_k(const float* __restrict__ h, float* psum, float* psumsq, int Nn) {
    int c = threadIdx.x & 63;
    int rg = threadIdx.x >> 6;   // 0..3
    float s = 0.f, s2 = 0.f;
    for (int r = blockIdx.x * 4 + rg; r < Nn; r += gridDim.x * 4) {
        float v = h[(long)r * C2 + c];
        s += v; s2 += v * v;
    }
    __shared__ float sh[256], sh2[256];
    sh[threadIdx.x] = s; sh2[threadIdx.x] = s2;
    __syncthreads();
    if (rg == 0) {
        s  = sh[c]  + sh[64 + c]  + sh[128 + c]  + sh[192 + c];
        s2 = sh2[c] + sh2[64 + c] + sh2[128 + c] + sh2[192 + c];
        psum[blockIdx.x * C2 + c]   = s;
        psumsq[blockIdx.x * C2 + c] = s2;
    }
}

__global__ void in_final_k(const float* psum, const float* psumsq,
                           float* meanv, float* rstdv, int Nn, int nb) {
    int c = threadIdx.x;
    if (c >= C2) return;
    float s = 0.f, s2 = 0.f;
    for (int b = 0; b < nb; b++) { s += psum[b * C2 + c]; s2 += psumsq[b * C2 + c]; }
    float m = s / (float)Nn;
    float var = s2 / (float)Nn - m * m;
    meanv[c] = m;
    rstdv[c] = rsqrtf(var + 1e-5f);
}

__global__ void norm_lsm_k(const float* __restrict__ h,
                           const float* __restrict__ meanv, const float* __restrict__ rstdv,
                           const float* __restrict__ gamma, const float* __restrict__ beta,
                           float* __restrict__ out, int Nn, long out_size) {
    __shared__ float sm[C2], sr[C2], sg[C2], sb[C2];
    if (threadIdx.x < C2) {
        sm[threadIdx.x] = meanv[threadIdx.x];
        sr[threadIdx.x] = rstdv[threadIdx.x];
        sg[threadIdx.x] = gamma[threadIdx.x];
        sb[threadIdx.x] = beta[threadIdx.x];
    }
    __syncthreads();

    int warp = threadIdx.x >> 5;
    int lane = threadIdx.x & 31;
    int r = blockIdx.x * (blockDim.x >> 5) + warp;
    if (r >= Nn) return;

    const int base = lane * 2;
    float2 v = *(const float2*)&h[(long)r * C2 + base];
    float y0 = (v.x - sm[base])     * sr[base]     * sg[base]     + sb[base];
    float y1 = (v.y - sm[base + 1]) * sr[base + 1] * sg[base + 1] + sb[base + 1];

    long NC = (long)Nn * C2;
    bool write_h = (out_size >= 2 * NC);
    if (write_h) {
        out[(long)r * C2 + base]     = y0;
        out[(long)r * C2 + base + 1] = y1;
    }
    // log_softmax over the 64 channels of this row
    float mx = fmaxf(y0, y1);
#pragma unroll
    for (int off = 16; off > 0; off >>= 1)
        mx = fmaxf(mx, __shfl_xor_sync(0xffffffff, mx, off));
    float s = __expf(y0 - mx) + __expf(y1 - mx);
#pragma unroll
    for (int off = 16; off > 0; off >>= 1)
        s += __shfl_xor_sync(0xffffffff, s, off);
    float lse = mx + __logf(s);

    float* out2 = out + (out_size - NC);
    out2[(long)r * C2 + base]     = y0 - lse;
    out2[(long)r * C2 + base + 1] = y1 - lse;
}

// ---------------------------------------------------------------------------
// Host launch
// ---------------------------------------------------------------------------
extern "C" void kernel_launch(void* const* d_in, const int* in_sizes, int n_in,
                              void* d_out, int out_size) {
    const float* x     = (const float*)d_in[0];
    const float* Wl1   = (const float*)d_in[1];
    const float* Wr1   = (const float*)d_in[2];
    const float* att1  = (const float*)d_in[3];
    const float* b1    = (const float*)d_in[4];
    const float* Wl2   = (const float*)d_in[5];
    const float* Wr2   = (const float*)d_in[6];
    const float* att2  = (const float*)d_in[7];
    const float* b2    = (const float*)d_in[8];
    const float* gamma = (const float*)d_in[9];
    const float* beta  = (const float*)d_in[10];
    const int*   ei    = (const int*)d_in[11];

    int Nn = in_sizes[0] / F_IN;        // 20000
    int E  = in_sizes[11] / 2;          // 320000
    if (Nn > MAXN) Nn = MAXN;
    if (E + Nn > MAXE) E = MAXE - Nn;

    float *xl1, *xr1, *h1, *xl2, *xr2, *h2, *psum, *psumsq, *meanv, *rstdv;
    int *counts, *cursor, *rowptr, *colv;
    cudaGetSymbolAddress((void**)&xl1, g_xl1);
    cudaGetSymbolAddress((void**)&xr1, g_xr1);
    cudaGetSymbolAddress((void**)&h1,  g_h1);
    cudaGetSymbolAddress((void**)&xl2, g_xl2);
    cudaGetSymbolAddress((void**)&xr2, g_xr2);
    cudaGetSymbolAddress((void**)&h2,  g_h2);
    cudaGetSymbolAddress((void**)&psum,   g_psum);
    cudaGetSymbolAddress((void**)&psumsq, g_psumsq);
    cudaGetSymbolAddress((void**)&meanv,  g_mean);
    cudaGetSymbolAddress((void**)&rstdv,  g_rstd);
    cudaGetSymbolAddress((void**)&counts, g_counts);
    cudaGetSymbolAddress((void**)&cursor, g_cursor);
    cudaGetSymbolAddress((void**)&rowptr, g_rowptr);
    cudaGetSymbolAddress((void**)&colv,   g_col);

    int total = E + Nn;

    // CSR build
    zero_counts_k<<<(Nn + 255) / 256, 256>>>(counts, Nn);
    count_k<<<(total + 255) / 256, 256>>>(ei, E, Nn, counts);
    scan_k<<<1, 1024>>>(counts, rowptr, cursor, Nn);
    scatter_k<<<(total + 255) / 256, 256>>>(ei, E, Nn, cursor, colv);

    // Layer 1 GEMMs: [N,128] @ [128,256] -> xl1, xr1 (A loaded once)
    {
        dim3 grid(HC1 / 64, (Nn + 63) / 64);
        sgemm_dual_k<<<grid, 256>>>(x, Wl1, Wr1, xl1, xr1, Nn, HC1, F_IN);
    }
    // Layer 1 attention + aggregate + bias + ELU
    gat_edge1_k<<<(Nn + 7) / 8, 256>>>(xl1, xr1, att1, b1, h1, rowptr, colv, Nn);

    // Layer 2 GEMMs: [N,256] @ [256,64] -> xl2, xr2
    {
        dim3 grid(C2 / 64, (Nn + 63) / 64);
        sgemm_dual_k<<<grid, 256>>>(h1, Wl2, Wr2, xl2, xr2, Nn, C2, HC1);
    }
    // Layer 2 attention + aggregate + bias
    gat_edge2_k<<<(Nn + 7) / 8, 256>>>(xl2, xr2, att2, b2, h2, rowptr, colv, Nn);

    // InstanceNorm stats
    in_partial_k<<<128, 256>>>(h2, psum, psumsq, Nn);
    in_final_k<<<1, 64>>>(psum, psumsq, meanv, rstdv, Nn, 128);

    // Normalize + log_softmax, write outputs
    norm_lsm_k<<<(Nn + 7) / 8, 256>>>(h2, meanv, rstdv, gamma, beta,
                                      (float*)d_out, Nn, (long)out_size);
}

// round 17
// speedup vs baseline: 1.2986x; 1.0059x over previous
#include <cuda_runtime.h>
#include <cuda_bf16.h>
#include <math.h>

// ---------------------------------------------------------------------------
// Problem constants (fixed by setup_inputs)
// ---------------------------------------------------------------------------
#define MAXN   20000
#define MAXE   340000   // 320000 edges + 20000 self loops
#define F_IN   128
#define HC1    256      // 8 heads * 32
#define C2     64
#define NSLOPE 0.2f

// ---------------------------------------------------------------------------
// Scratch (static __device__ globals; no allocation anywhere)
// ---------------------------------------------------------------------------
__device__ float g_xl1[MAXN * HC1];
__device__ float g_xr1[MAXN * HC1];
__device__ float g_h1 [MAXN * HC1];
__device__ float g_xl2[MAXN * C2];
__device__ float g_xr2[MAXN * C2];
__device__ float g_h2 [MAXN * C2];
__device__ int   g_counts[MAXN];
__device__ int   g_cursor[MAXN];
__device__ int   g_rowptr[MAXN + 1];
__device__ int   g_col   [MAXE + 32];
__device__ float g_psum  [128 * C2];
__device__ float g_psumsq[128 * C2];
__device__ float g_mean[C2];
__device__ float g_rstd[C2];

// ---------------------------------------------------------------------------
// CSR build (measured form)
// ---------------------------------------------------------------------------
__global__ void zero_counts_k(int* counts, int n) {
    int i = blockIdx.x * blockDim.x + threadIdx.x;
    if (i < n) counts[i] = 0;
}

__global__ void count_k(const int* ei, int E, int Nn, int* counts) {
    int i = blockIdx.x * blockDim.x + threadIdx.x;
    int total = E + Nn;
    if (i >= total) return;
    int d = (i < E) ? ei[E + i] : (i - E);   // dst row of edge_index, or self loop
    atomicAdd(&counts[d], 1);
}

// Single block, 1024 threads; serial chunk scan + 10-step block scan (validated R13).
__global__ void scan_k(const int* counts, int* rowptr, int* cursor, int Nn) {
    __shared__ int sh[1024];
    int t = threadIdx.x;
    int per = (Nn + 1023) >> 10;
    int beg = t * per;
    int end = min(beg + per, Nn);
    int sum = 0;
    for (int i = beg; i < end; i++) sum += counts[i];
    sh[t] = sum;
    __syncthreads();
    for (int off = 1; off < 1024; off <<= 1) {
        int v = (t >= off) ? sh[t - off] : 0;
        __syncthreads();
        sh[t] += v;
        __syncthreads();
    }
    int run = sh[t] - sum;   // exclusive prefix of this chunk
    for (int i = beg; i < end; i++) {
        int c = counts[i];
        rowptr[i] = run;
        cursor[i] = run;
        run += c;
    }
    if (t == 1023) rowptr[Nn] = sh[1023];
}

__global__ void scatter_k(const int* ei, int E, int Nn, int* cursor, int* col) {
    int i = blockIdx.x * blockDim.x + threadIdx.x;
    int total = E + Nn;
    if (i >= total) return;
    int s, d;
    if (i < E) { s = ei[i]; d = ei[E + i]; }
    else       { s = d = i - E; }
    int pos = atomicAdd(&cursor[d], 1);
    col[pos] = s;
}

// ---------------------------------------------------------------------------
// Dual-B SGEMM, 64x64/4x4 with register-prefetch double buffering (validated R14).
// ---------------------------------------------------------------------------
__global__ void sgemm_dual_k(const float* __restrict__ A,
                             const float* __restrict__ B0, const float* __restrict__ B1,
                             float* __restrict__ C0, float* __restrict__ C1,
                             int M, int N, int K) {
    __shared__ float As [16][65];   // [k][m], padded
    __shared__ float Bs0[16][64];   // [k][n]
    __shared__ float Bs1[16][64];
    const int tid = threadIdx.x;
    const int tx = tid % 16;       // n quad
    const int ty = tid / 16;       // m quad
    const int row0 = blockIdx.y * 64;
    const int col0 = blockIdx.x * 64;

    // Fixed per-thread load coordinates
    int am[4], ak[4], bk[4], bn[4];
#pragma unroll
    for (int i = 0; i < 4; i++) {
        int idx = tid + i * 256;
        am[i] = idx >> 4;
        ak[i] = idx & 15;
        bk[i] = idx >> 6;
        bn[i] = idx & 63;
    }

    float acc0[4][4] = {};
    float acc1[4][4] = {};

    // Prologue: tile 0 -> registers
    float ra[4], rb0[4], rb1[4];
#pragma unroll
    for (int i = 0; i < 4; i++) {
        int gm = row0 + am[i];
        ra[i] = (gm < M) ? A[(long)gm * K + ak[i]] : 0.f;
        long off = (long)bk[i] * N + col0 + bn[i];
        rb0[i] = B0[off];
        rb1[i] = B1[off];
    }

    for (int k0 = 0; k0 < K; k0 += 16) {
        // Commit prefetched tile to SMEM
#pragma unroll
        for (int i = 0; i < 4; i++) {
            As[ak[i]][am[i]]  = ra[i];
            Bs0[bk[i]][bn[i]] = rb0[i];
            Bs1[bk[i]][bn[i]] = rb1[i];
        }
        __syncthreads();

        // Prefetch next tile into registers (overlaps with compute)
        int k1 = k0 + 16;
        if (k1 < K) {
#pragma unroll
            for (int i = 0; i < 4; i++) {
                int gm = row0 + am[i];
                ra[i] = (gm < M) ? A[(long)gm * K + k1 + ak[i]] : 0.f;
                long off = (long)(k1 + bk[i]) * N + col0 + bn[i];
                rb0[i] = B0[off];
                rb1[i] = B1[off];
            }
        }

#pragma unroll
        for (int kk = 0; kk < 16; kk++) {
            float a[4], b0[4], b1[4];
#pragma unroll
            for (int i = 0; i < 4; i++) a[i] = As[kk][ty * 4 + i];
#pragma unroll
            for (int j = 0; j < 4; j++) { b0[j] = Bs0[kk][tx * 4 + j]; b1[j] = Bs1[kk][tx * 4 + j]; }
#pragma unroll
            for (int i = 0; i < 4; i++)
#pragma unroll
                for (int j = 0; j < 4; j++) {
                    acc0[i][j] += a[i] * b0[j];
                    acc1[i][j] += a[i] * b1[j];
                }
        }
        __syncthreads();
    }
#pragma unroll
    for (int i = 0; i < 4; i++) {
        int gm = row0 + ty * 4 + i;
        if (gm < M) {
            float4 v0 = make_float4(acc0[i][0], acc0[i][1], acc0[i][2], acc0[i][3]);
            float4 v1 = make_float4(acc1[i][0], acc1[i][1], acc1[i][2], acc1[i][3]);
            *(float4*)&C0[(long)gm * N + col0 + tx * 4] = v0;
            *(float4*)&C1[(long)gm * N + col0 + tx * 4] = v1;
        }
    }
}

// ---------------------------------------------------------------------------
// Layer-1 edge kernel: one warp per dst; 2 edges per iteration (validated R14).
// ---------------------------------------------------------------------------
__global__ void gat_edge1_k(const float* __restrict__ xl, const float* __restrict__ xr,
                            const float* __restrict__ att, const float* __restrict__ bias,
                            float* __restrict__ hout,
                            const int* __restrict__ rowptr, const int* __restrict__ col,
                            int Nn) {
    __shared__ float s_att[HC1];
    __shared__ float s_b[HC1];
    if (threadIdx.x < HC1) { s_att[threadIdx.x] = att[threadIdx.x]; s_b[threadIdx.x] = bias[threadIdx.x]; }
    __syncthreads();

    int warp = threadIdx.x >> 5;
    int lane = threadIdx.x & 31;
    int d = blockIdx.x * (blockDim.x >> 5) + warp;
    if (d >= Nn) return;

    const int base = lane * 8;
    float xrv[8], a[8];
    {
        float4 t0 = *(const float4*)&xr[(long)d * HC1 + base];
        float4 t1 = *(const float4*)&xr[(long)d * HC1 + base + 4];
        xrv[0]=t0.x; xrv[1]=t0.y; xrv[2]=t0.z; xrv[3]=t0.w;
        xrv[4]=t1.x; xrv[5]=t1.y; xrv[6]=t1.z; xrv[7]=t1.w;
    }
#pragma unroll
    for (int j = 0; j < 8; j++) a[j] = s_att[base + j];

    float acc[8] = {0,0,0,0,0,0,0,0};
    float denom = 0.f;

    int beg = rowptr[d], end = rowptr[d + 1];
    int sA = (beg < end) ? col[beg] : 0;
    int sB = (beg + 1 < end) ? col[beg + 1] : 0;

    int e = beg;
    while (e < end) {
        bool has2 = (e + 1 < end);
        // Prefetch next pair's indices
        int sA2 = (e + 2 < end) ? col[e + 2] : 0;
        int sB2 = (e + 3 < end) ? col[e + 3] : 0;

        // Issue both edges' feature loads back-to-back (MLP=2)
        const float4* pA = (const float4*)&xl[(long)sA * HC1 + base];
        float4 va0 = __ldg(pA);
        float4 va1 = __ldg(pA + 1);
        float4 vb0 = make_float4(0,0,0,0), vb1 = make_float4(0,0,0,0);
        if (has2) {
            const float4* pB = (const float4*)&xl[(long)sB * HC1 + base];
            vb0 = __ldg(pB);
            vb1 = __ldg(pB + 1);
        }

        // Edge A
        {
            float xls[8] = {va0.x, va0.y, va0.z, va0.w, va1.x, va1.y, va1.z, va1.w};
            float sc = 0.f;
#pragma unroll
            for (int j = 0; j < 8; j++) {
                float u = xls[j] + xrv[j];
                float t = (u > 0.f) ? u : NSLOPE * u;
                sc += t * a[j];
            }
            sc += __shfl_xor_sync(0xffffffff, sc, 1);
            sc += __shfl_xor_sync(0xffffffff, sc, 2);
            float ex = __expf(sc);
            denom += ex;
#pragma unroll
            for (int j = 0; j < 8; j++) acc[j] += ex * xls[j];
        }
        // Edge B
        if (has2) {
            float xls[8] = {vb0.x, vb0.y, vb0.z, vb0.w, vb1.x, vb1.y, vb1.z, vb1.w};
            float sc = 0.f;
#pragma unroll
            for (int j = 0; j < 8; j++) {
                float u = xls[j] + xrv[j];
                float t = (u > 0.f) ? u : NSLOPE * u;
                sc += t * a[j];
            }
            sc += __shfl_xor_sync(0xffffffff, sc, 1);
            sc += __shfl_xor_sync(0xffffffff, sc, 2);
            float ex = __expf(sc);
            denom += ex;
#pragma unroll
            for (int j = 0; j < 8; j++) acc[j] += ex * xls[j];
        }

        sA = sA2; sB = sB2;
        e += 2;
    }
    float inv = 1.f / (denom + 1e-16f);
#pragma unroll
    for (int j = 0; j < 8; j++) {
        float v = acc[j] * inv + s_b[base + j];
        v = (v > 0.f) ? v : expm1f(v);   // ELU
        hout[(long)d * HC1 + base + j] = v;
    }
}

// ---------------------------------------------------------------------------
// Layer-2 edge kernel: one warp per dst, 2 values/lane, 2 edges per iteration
// (same ILP transform as edge1; accumulation order preserved).
// ---------------------------------------------------------------------------
__global__ void gat_edge2_k(const float* __restrict__ xl, const float* __restrict__ xr,
                            const float* __restrict__ att, const float* __restrict__ bias,
                            float* __restrict__ hout,
                            const int* __restrict__ rowptr, const int* __restrict__ col,
                            int Nn) {
    __shared__ float s_att[C2];
    __shared__ float s_b[C2];
    if (threadIdx.x < C2) { s_att[threadIdx.x] = att[threadIdx.x]; s_b[threadIdx.x] = bias[threadIdx.x]; }
    __syncthreads();

    int warp = threadIdx.x >> 5;
    int lane = threadIdx.x & 31;
    int d = blockIdx.x * (blockDim.x >> 5) + warp;
    if (d >= Nn) return;

    const int base = lane * 2;
    float2 xrv = *(const float2*)&xr[(long)d * C2 + base];
    float a0 = s_att[base], a1 = s_att[base + 1];
    float acc0 = 0.f, acc1 = 0.f, denom = 0.f;

    int beg = rowptr[d], end = rowptr[d + 1];
    int sA = (beg < end) ? col[beg] : 0;
    int sB = (beg + 1 < end) ? col[beg + 1] : 0;

    int e = beg;
    while (e < end) {
        bool has2 = (e + 1 < end);
        int sA2 = (e + 2 < end) ? col[e + 2] : 0;
        int sB2 = (e + 3 < end) ? col[e + 3] : 0;

        // Both feature loads issued back-to-back (MLP=2)
        float2 vA = __ldg((const float2*)&xl[(long)sA * C2 + base]);
        float2 vB = make_float2(0.f, 0.f);
        if (has2) vB = __ldg((const float2*)&xl[(long)sB * C2 + base]);

        // Edge A
        {
            float u0 = vA.x + xrv.x; float t0 = (u0 > 0.f) ? u0 : NSLOPE * u0;
            float u1 = vA.y + xrv.y; float t1 = (u1 > 0.f) ? u1 : NSLOPE * u1;
            float sc = t0 * a0 + t1 * a1;
#pragma unroll
            for (int off = 16; off > 0; off >>= 1)
                sc += __shfl_xor_sync(0xffffffff, sc, off);
            float ex = __expf(sc);
            denom += ex;
            acc0 += ex * vA.x;
            acc1 += ex * vA.y;
        }
        // Edge B
        if (has2) {
            float u0 = vB.x + xrv.x; float t0 = (u0 > 0.f) ? u0 : NSLOPE * u0;
            float u1 = vB.y + xrv.y; float t1 = (u1 > 0.f) ? u1 : NSLOPE * u1;
            float sc = t0 * a0 + t1 * a1;
#pragma unroll
            for (int off = 16; off > 0; off >>= 1)
                sc += __shfl_xor_sync(0xffffffff, sc, off);
            float ex = __expf(sc);
            denom += ex;
            acc0 += ex * vB.x;
            acc1 += ex * vB.y;
        }

        sA = sA2; sB = sB2;
        e += 2;
    }
    float inv = 1.f / (denom + 1e-16f);
    hout[(long)d * C2 + base]     = acc0 * inv + s_b[base];
    hout[(long)d * C2 + base + 1] = acc1 * inv + s_b[base + 1];
}

// ---------------------------------------------------------------------------
// InstanceNorm stats (deterministic two-level reduction) + norm + log_softmax
// ---------------------------------------------------------------------------
__global__ void in_partial_k(const float* __restrict__ h, float* psum, float* psumsq, int Nn) {
    int c = threadIdx.x & 63;
    int rg = threadIdx.x >> 6;   // 0..3
    float s = 0.f, s2 = 0.f;
    for (int r = blockIdx.x * 4 + rg; r < Nn; r += gridDim.x * 4) {
        float v = h[(long)r * C2 + c];
        s += v; s2 += v * v;
    }
    __shared__ float sh[256], sh2[256];
    sh[threadIdx.x] = s; sh2[threadIdx.x] = s2;
    __syncthreads();
    if (rg == 0) {
        s  = sh[c]  + sh[64 + c]  + sh[128 + c]  + sh[192 + c];
        s2 = sh2[c] + sh2[64 + c] + sh2[128 + c] + sh2[192 + c];
        psum[blockIdx.x * C2 + c]   = s;
        psumsq[blockIdx.x * C2 + c] = s2;
    }
}

__global__ void in_final_k(const float* psum, const float* psumsq,
                           float* meanv, float* rstdv, int Nn, int nb) {
    int c = threadIdx.x;
    if (c >= C2) return;
    float s = 0.f, s2 = 0.f;
    for (int b = 0; b < nb; b++) { s += psum[b * C2 + c]; s2 += psumsq[b * C2 + c]; }
    float m = s / (float)Nn;
    float var = s2 / (float)Nn - m * m;
    meanv[c] = m;
    rstdv[c] = rsqrtf(var + 1e-5f);
}

__global__ void norm_lsm_k(const float* __restrict__ h,
                           const float* __restrict__ meanv, const float* __restrict__ rstdv,
                           const float* __restrict__ gamma, const float* __restrict__ beta,
                           float* __restrict__ out, int Nn, long out_size) {
    __shared__ float sm[C2], sr[C2], sg[C2], sb[C2];
    if (threadIdx.x < C2) {
        sm[threadIdx.x] = meanv[threadIdx.x];
        sr[threadIdx.x] = rstdv[threadIdx.x];
        sg[threadIdx.x] = gamma[threadIdx.x];
        sb[threadIdx.x] = beta[threadIdx.x];
    }
    __syncthreads();

    int warp = threadIdx.x >> 5;
    int lane = threadIdx.x & 31;
    int r = blockIdx.x * (blockDim.x >> 5) + warp;
    if (r >= Nn) return;

    const int base = lane * 2;
    float2 v = *(const float2*)&h[(long)r * C2 + base];
    float y0 = (v.x - sm[base])     * sr[base]     * sg[base]     + sb[base];
    float y1 = (v.y - sm[base + 1]) * sr[base + 1] * sg[base + 1] + sb[base + 1];

    long NC = (long)Nn * C2;
    bool write_h = (out_size >= 2 * NC);
    if (write_h) {
        out[(long)r * C2 + base]     = y0;
        out[(long)r * C2 + base + 1] = y1;
    }
    // log_softmax over the 64 channels of this row
    float mx = fmaxf(y0, y1);
#pragma unroll
    for (int off = 16; off > 0; off >>= 1)
        mx = fmaxf(mx, __shfl_xor_sync(0xffffffff, mx, off));
    float s = __expf(y0 - mx) + __expf(y1 - mx);
#pragma unroll
    for (int off = 16; off > 0; off >>= 1)
        s += __shfl_xor_sync(0xffffffff, s, off);
    float lse = mx + __logf(s);

    float* out2 = out + (out_size - NC);
    out2[(long)r * C2 + base]     = y0 - lse;
    out2[(long)r * C2 + base + 1] = y1 - lse;
}

// ---------------------------------------------------------------------------
// Host launch
// ---------------------------------------------------------------------------
extern "C" void kernel_launch(void* const* d_in, const int* in_sizes, int n_in,
                              void* d_out, int out_size) {
    const float* x     = (const float*)d_in[0];
    const float* Wl1   = (const float*)d_in[1];
    const float* Wr1   = (const float*)d_in[2];
    const float* att1  = (const float*)d_in[3];
    const float* b1    = (const float*)d_in[4];
    const float* Wl2   = (const float*)d_in[5];
    const float* Wr2   = (const float*)d_in[6];
    const float* att2  = (const float*)d_in[7];
    const float* b2    = (const float*)d_in[8];
    const float* gamma = (const float*)d_in[9];
    const float* beta  = (const float*)d_in[10];
    const int*   ei    = (const int*)d_in[11];

    int Nn = in_sizes[0] / F_IN;        // 20000
    int E  = in_sizes[11] / 2;          // 320000
    if (Nn > MAXN) Nn = MAXN;
    if (E + Nn > MAXE) E = MAXE - Nn;

    float *xl1, *xr1, *h1, *xl2, *xr2, *h2, *psum, *psumsq, *meanv, *rstdv;
    int *counts, *cursor, *rowptr, *colv;
    cudaGetSymbolAddress((void**)&xl1, g_xl1);
    cudaGetSymbolAddress((void**)&xr1, g_xr1);
    cudaGetSymbolAddress((void**)&h1,  g_h1);
    cudaGetSymbolAddress((void**)&xl2, g_xl2);
    cudaGetSymbolAddress((void**)&xr2, g_xr2);
    cudaGetSymbolAddress((void**)&h2,  g_h2);
    cudaGetSymbolAddress((void**)&psum,   g_psum);
    cudaGetSymbolAddress((void**)&psumsq, g_psumsq);
    cudaGetSymbolAddress((void**)&meanv,  g_mean);
    cudaGetSymbolAddress((void**)&rstdv,  g_rstd);
    cudaGetSymbolAddress((void**)&counts, g_counts);
    cudaGetSymbolAddress((void**)&cursor, g_cursor);
    cudaGetSymbolAddress((void**)&rowptr, g_rowptr);
    cudaGetSymbolAddress((void**)&colv,   g_col);

    int total = E + Nn;

    // CSR build
    zero_counts_k<<<(Nn + 255) / 256, 256>>>(counts, Nn);
    count_k<<<(total + 255) / 256, 256>>>(ei, E, Nn, counts);
    scan_k<<<1, 1024>>>(counts, rowptr, cursor, Nn);
    scatter_k<<<(total + 255) / 256, 256>>>(ei, E, Nn, cursor, colv);

    // Layer 1 GEMMs: [N,128] @ [128,256] -> xl1, xr1 (A loaded once)
    {
        dim3 grid(HC1 / 64, (Nn + 63) / 64);
        sgemm_dual_k<<<grid, 256>>>(x, Wl1, Wr1, xl1, xr1, Nn, HC1, F_IN);
    }
    // Layer 1 attention + aggregate + bias + ELU
    gat_edge1_k<<<(Nn + 7) / 8, 256>>>(xl1, xr1, att1, b1, h1, rowptr, colv, Nn);

    // Layer 2 GEMMs: [N,256] @ [256,64] -> xl2, xr2
    {
        dim3 grid(C2 / 64, (Nn + 63) / 64);
        sgemm_dual_k<<<grid, 256>>>(h1, Wl2, Wr2, xl2, xr2, Nn, C2, HC1);
    }
    // Layer 2 attention + aggregate + bias
    gat_edge2_k<<<(Nn + 7) / 8, 256>>>(xl2, xr2, att2, b2, h2, rowptr, colv, Nn);

    // InstanceNorm stats
    in_partial_k<<<128, 256>>>(h2, psum, psumsq, Nn);
    in_final_k<<<1, 64>>>(psum, psumsq, meanv, rstdv, Nn, 128);

    // Normalize + log_softmax, write outputs
    norm_lsm_k<<<(Nn + 7) / 8, 256>>>(h2, meanv, rstdv, gamma, beta,
                                      (float*)d_out, Nn, (long)out_size);
}